// round 9
// baseline (speedup 1.0000x reference)
#include <cuda_runtime.h>
#include <math.h>

#define FS     39      // total fields
#define NF     38      // fields in pairwise term (0..37)
#define NP     703     // NF*(NF-1)/2 pairs
#define NITEM  (NP*5)  // 3515 items
#define FEAT   100000
#define EMB    10
#define ROWB   (EMB*4) // 40 bytes per embedding row
#define TPB    256
#define SLICES 3
#define KMAX   5       // items per thread per slice (3*256*5 = 3840 >= 3515)
#define NPPAD  820     // max pair index touched = floor(4095/5) = 819
#define BATCH  2048

__device__ float g_acc[BATCH];   // zero-init; self-cleaned every launch
__device__ int   g_cnt[BATCH];   // zero-init; self-cleaned every launch

__global__ __launch_bounds__(TPB) void ffm_kernel(
    const int*   __restrict__ idxs,   // [B, FS]
    const float* __restrict__ vals,   // [B, FS]
    const float* __restrict__ emb,    // [FS, FEAT, EMB]
    const float* __restrict__ w1,     // [FEAT]
    float*       __restrict__ out)    // [B]
{
    __shared__ int   s_idx[FS];
    __shared__ float s_val[FS];
    __shared__ int4  s_pair[NPPAD];   // {byteOffA, byteOffB, bits(v_i*v_j), pad}
    __shared__ float s_red[TPB / 32];

    const int s = blockIdx.x;         // slice 0..2
    const int b = blockIdx.y;         // batch element
    const int t = threadIdx.x;

    if (t < FS) {
        s_idx[t] = idxs[b * FS + t];
        s_val[t] = vals[b * FS + t];
    }
    __syncthreads();

    // Zero-scale padding: uniform KMAX iterations, no guard. Padding items
    // hit emb[0] (hot in L2) with scale 0.
    for (int p = NP + t; p < NPPAD; p += TPB) {
        s_pair[p] = make_int4(0, 0, 0, 0);
    }

    // Prologue: closed-form triangular decode p -> (i, j); byte-offset
    // descriptors. base(i) = i*(75-i)/2 for NF=38.
    for (int p = t; p < NP; p += TPB) {
        int i = (int)((75.0f - sqrtf(5625.0f - 8.0f * (float)p)) * 0.5f);
        if (p < i * (75 - i) / 2) --i;
        else if (p >= (i + 1) * (74 - i) / 2) ++i;
        const int base = i * (75 - i) / 2;
        const int j = p - base + i + 1;
        int4 d;
        d.x = (i * FEAT + s_idx[j]) * ROWB;   // emb[i][idx_j] byte offset
        d.y = (j * FEAT + s_idx[i]) * ROWB;   // emb[j][idx_i] byte offset
        d.z = __float_as_int(s_val[i] * s_val[j]);
        d.w = 0;
        s_pair[p] = d;
    }

    float acc = 0.f;
    if (s == 0 && t < FS) {
        acc = w1[s_idx[t]] * s_val[t];        // first-order term (slice 0 only)
    }
    __syncthreads();

    // Main loop: this slice handles items k*768 + s*256 + t, k = 0..4.
    // Stride 768 = 153*5 + 3 over (pair, chunk-byte).
    const char* __restrict__ embB = (const char*)emb;
    const int item0 = s * TPB + t;
    int p  = item0 / 5;
    int cb = (item0 - p * 5) * 8;

    #pragma unroll
    for (int k = 0; k < KMAX; ++k) {
        const int4 d = s_pair[p];
        const float2 a = *(const float2*)(embB + (unsigned)(d.x + cb));
        const float2 v = *(const float2*)(embB + (unsigned)(d.y + cb));
        acc += __int_as_float(d.z) * (a.x * v.x + a.y * v.y);
        p += 153; cb += 24;
        if (cb >= ROWB) { cb -= ROWB; ++p; }
    }

    // Block reduction.
    #pragma unroll
    for (int o = 16; o > 0; o >>= 1)
        acc += __shfl_down_sync(0xffffffffu, acc, o);
    if ((t & 31) == 0) s_red[t >> 5] = acc;
    __syncthreads();

    // Cross-slice combine: last-arriving CTA finalizes and self-cleans the
    // scratch so every graph replay starts from zeroed state.
    if (t == 0) {
        float cta = 0.f;
        #pragma unroll
        for (int w = 0; w < TPB / 32; w++) cta += s_red[w];
        atomicAdd(&g_acc[b], cta);
        __threadfence();
        const int prev = atomicAdd(&g_cnt[b], 1);
        if (prev == SLICES - 1) {
            const float tot = g_acc[b];
            out[b] = 1.f / (1.f + expf(-tot));
            g_acc[b] = 0.f;
            g_cnt[b] = 0;
        }
    }
}

extern "C" void kernel_launch(void* const* d_in, const int* in_sizes, int n_in,
                              void* d_out, int out_size) {
    const int*   idxs = (const int*)d_in[0];
    const float* vals = (const float*)d_in[1];
    const float* emb  = (const float*)d_in[2];
    const float* w1   = (const float*)d_in[3];
    float* out = (float*)d_out;

    dim3 grid(SLICES, BATCH);
    ffm_kernel<<<grid, TPB>>>(idxs, vals, emb, w1, out);
}